// round 5
// baseline (speedup 1.0000x reference)
#include <cuda_runtime.h>
#include <math.h>
#include <stdint.h>

// ------------------------------------------------------------------
// Problem constants: B=8, M=1024, C=768
// ------------------------------------------------------------------
#define BATCH 8
#define SEQ   1024
#define CH    768

// Scratch (device globals; allocation-free per harness rules)
__device__ __align__(16) float g_qkv   [BATCH * SEQ * (3 * CH)];
__device__ __align__(16) float g_scores[BATCH * SEQ * SEQ];
__device__ __align__(16) float g_lo    [BATCH * SEQ * CH];
__device__ __align__(16) float g_cq    [BATCH * SEQ * CH];
__device__ __align__(16) float g_kv    [BATCH * SEQ * (2 * CH)];
__device__ __align__(16) float g_merge [BATCH * SEQ * CH];
// Transposed operands
__device__ __align__(16) float g_wqkvT [3 * CH * CH];
__device__ __align__(16) float g_wqT   [CH * CH];
__device__ __align__(16) float g_wkvT  [2 * CH * CH];
__device__ __align__(16) float g_wffnT [CH * CH];
__device__ __align__(16) float g_vT    [BATCH * CH * SEQ];
__device__ __align__(16) float g_cvT   [BATCH * CH * SEQ];
// Softmax row stats
__device__ __align__(16) float g_statm [BATCH * SEQ];   // row max
__device__ __align__(16) float g_stati [BATCH * SEQ];   // 1 / row sum(exp)

#define BM 128
#define BN 128
#define BK 16

// ------------------------------------------------------------------
// TF32 helpers
// ------------------------------------------------------------------
__device__ __forceinline__ unsigned f2tf32(float x) {
    unsigned u;
    asm("cvt.rna.tf32.f32 %0, %1;" : "=r"(u) : "f"(x));
    return u;
}

__device__ __forceinline__ void mma_tf32(float* d, const unsigned* a, const unsigned* b) {
    asm volatile(
        "mma.sync.aligned.m16n8k8.row.col.f32.tf32.tf32.f32 "
        "{%0,%1,%2,%3}, {%4,%5,%6,%7}, {%8,%9}, {%0,%1,%2,%3};\n"
        : "+f"(d[0]), "+f"(d[1]), "+f"(d[2]), "+f"(d[3])
        : "r"(a[0]), "r"(a[1]), "r"(a[2]), "r"(a[3]),
          "r"(b[0]), "r"(b[1]));
}

// Swizzled k-major tile storage: flat [row*16 + pos],
// pos(k,row) = (((k&3) + (row>>1)) & 3)*4 + (k>>2)
__device__ __forceinline__ void store_tile_swz(unsigned* S, int row, int q, float4 v) {
    const int h = (row >> 1) & 3;
    unsigned* base = S + row * 16 + q;
    base[(((0 + h) & 3) << 2)] = f2tf32(v.x);
    base[(((1 + h) & 3) << 2)] = f2tf32(v.y);
    base[(((2 + h) & 3) << 2)] = f2tf32(v.z);
    base[(((3 + h) & 3) << 2)] = f2tf32(v.w);
}

__device__ __forceinline__ uint4 ld_frag_swz(const unsigned* S, int row, int c) {
    const int g = (c + (row >> 1)) & 3;
    return *(const uint4*)(S + row * 16 + (g << 2));
}

// ------------------------------------------------------------------
// Unified NT GEMM: C[m,n] = sum_k A[m,k] * B[n,k]
//   MASKED: masked score epilogue (scale / -10000)
//   SOFT:   A-staging applies exp(a - rowmax); epilogue scales by 1/rowsum
//   else:   + bias[n] if bias != nullptr
// Single-buffered (proven R2 loop), one CTA = 256 thr, 8 warps 32x64.
// ------------------------------------------------------------------
template<bool MASKED, bool SOFT>
__global__ void __launch_bounds__(256, 2) gemm_nt(
    const float* __restrict__ A, int lda, long long strideA,
    const float* __restrict__ B, int ldb, long long strideB,
    const float* __restrict__ bias,
    const float* __restrict__ mask, float scale,
    const float* __restrict__ statm, const float* __restrict__ stati,
    float* __restrict__ C, int ldc, long long strideC,
    int K)
{
    __shared__ unsigned As[BM * BK];
    __shared__ unsigned Bs[BN * BK];

    const int b = blockIdx.z;
    A += (size_t)b * strideA;
    B += (size_t)b * strideB;
    C += (size_t)b * strideC;
    const float* mrow = MASKED ? (mask + (size_t)b * SEQ) : nullptr;

    const int tid  = threadIdx.x;
    const int lane = tid & 31;
    const int wid  = tid >> 5;
    const int wm = wid & 3;
    const int wn = wid >> 2;
    const int m0 = blockIdx.y * BM;
    const int n0 = blockIdx.x * BN;
    const int c  = lane & 3;
    const int g4 = lane >> 2;

    const int ar = tid >> 2, aq = tid & 3;

    const float* Ap = A + (size_t)(m0 + ar) * lda + 4 * aq;
    const float* Bp = B + (size_t)(n0 + ar) * ldb + 4 * aq;

    // Per-thread softmax stats for the two A rows this thread stages.
    float sm0 = 0.f, sm1 = 0.f;
    if (SOFT) {
        const float* mbase = statm + (size_t)b * SEQ + m0;
        sm0 = mbase[ar];
        sm1 = mbase[ar + 64];
    }

    float acc[2][8][4];
    #pragma unroll
    for (int i = 0; i < 2; i++)
        #pragma unroll
        for (int j = 0; j < 8; j++)
            #pragma unroll
            for (int q = 0; q < 4; q++) acc[i][j][q] = 0.f;

    float4 pa0 = *(const float4*)Ap;
    float4 pa1 = *(const float4*)(Ap + (size_t)64 * lda);
    float4 pb0 = *(const float4*)Bp;
    float4 pb1 = *(const float4*)(Bp + (size_t)64 * ldb);

    const int niter = K / BK;
    for (int kt = 0; kt < niter; kt++) {
        if (SOFT) {
            pa0.x = __expf(pa0.x - sm0); pa0.y = __expf(pa0.y - sm0);
            pa0.z = __expf(pa0.z - sm0); pa0.w = __expf(pa0.w - sm0);
            pa1.x = __expf(pa1.x - sm1); pa1.y = __expf(pa1.y - sm1);
            pa1.z = __expf(pa1.z - sm1); pa1.w = __expf(pa1.w - sm1);
        }
        store_tile_swz(As, ar,      aq, pa0);
        store_tile_swz(As, ar + 64, aq, pa1);
        store_tile_swz(Bs, ar,      aq, pb0);
        store_tile_swz(Bs, ar + 64, aq, pb1);
        __syncthreads();

        if (kt + 1 < niter) {
            const float* An = Ap + (kt + 1) * BK;
            pa0 = *(const float4*)An;
            pa1 = *(const float4*)(An + (size_t)64 * lda);
            const float* Bn = Bp + (kt + 1) * BK;
            pb0 = *(const float4*)Bn;
            pb1 = *(const float4*)(Bn + (size_t)64 * ldb);
        }

        unsigned af[2][2][4];
        #pragma unroll
        for (int mt = 0; mt < 2; mt++) {
            const int r = wm * 32 + mt * 16 + g4;
            uint4 lo = ld_frag_swz(As, r,     c);
            uint4 hi = ld_frag_swz(As, r + 8, c);
            af[mt][0][0] = lo.x; af[mt][0][1] = hi.x;
            af[mt][0][2] = lo.y; af[mt][0][3] = hi.y;
            af[mt][1][0] = lo.z; af[mt][1][1] = hi.z;
            af[mt][1][2] = lo.w; af[mt][1][3] = hi.w;
        }

        #pragma unroll
        for (int nt = 0; nt < 8; nt++) {
            uint4 bv = ld_frag_swz(Bs, wn * 64 + nt * 8 + g4, c);
            unsigned b0[2] = { bv.x, bv.y };
            unsigned b1[2] = { bv.z, bv.w };
            #pragma unroll
            for (int mt = 0; mt < 2; mt++) {
                mma_tf32(acc[mt][nt], af[mt][0], b0);
                mma_tf32(acc[mt][nt], af[mt][1], b1);
            }
        }
        __syncthreads();
    }

    // Epilogue
    #pragma unroll
    for (int mt = 0; mt < 2; mt++) {
        const int r0 = m0 + wm * 32 + mt * 16 + g4;
        float mr0 = 0.f, mr1 = 0.f, il0 = 1.f, il1 = 1.f;
        if (MASKED) { mr0 = mrow[r0]; mr1 = mrow[r0 + 8]; }
        if (SOFT) {
            const float* ib = stati + (size_t)b * SEQ;
            il0 = ib[r0]; il1 = ib[r0 + 8];
        }
        #pragma unroll
        for (int nt = 0; nt < 8; nt++) {
            const int col = n0 + wn * 64 + nt * 8 + 2 * c;
            float2 v0, v1;
            if (MASKED) {
                const float mn0 = mrow[col];
                const float mn1 = mrow[col + 1];
                v0.x = (mr0 != 0.f && mn0 != 0.f) ? acc[mt][nt][0] * scale : -10000.f;
                v0.y = (mr0 != 0.f && mn1 != 0.f) ? acc[mt][nt][1] * scale : -10000.f;
                v1.x = (mr1 != 0.f && mn0 != 0.f) ? acc[mt][nt][2] * scale : -10000.f;
                v1.y = (mr1 != 0.f && mn1 != 0.f) ? acc[mt][nt][3] * scale : -10000.f;
            } else if (SOFT) {
                v0 = make_float2(acc[mt][nt][0] * il0, acc[mt][nt][1] * il0);
                v1 = make_float2(acc[mt][nt][2] * il1, acc[mt][nt][3] * il1);
            } else {
                float bx = 0.f, by = 0.f;
                if (bias) { bx = bias[col]; by = bias[col + 1]; }
                v0 = make_float2(acc[mt][nt][0] + bx, acc[mt][nt][1] + by);
                v1 = make_float2(acc[mt][nt][2] + bx, acc[mt][nt][3] + by);
            }
            *(float2*)(C + (size_t)r0 * ldc + col) = v0;
            *(float2*)(C + (size_t)(r0 + 8) * ldc + col) = v1;
        }
    }
}

// ------------------------------------------------------------------
// Batched tiled transpose: out[c][r] = in[r][c]
// ------------------------------------------------------------------
__global__ void __launch_bounds__(256) transpose_k(
    const float* __restrict__ in, int ldi, long long sIn,
    float* __restrict__ out, int ldo, long long sOut)
{
    __shared__ float t[32][33];
    const int b = blockIdx.z;
    in  += (size_t)b * sIn;
    out += (size_t)b * sOut;
    const int r0 = blockIdx.y * 32;
    const int c0 = blockIdx.x * 32;
    const int tx = threadIdx.x & 31;
    const int ty = threadIdx.x >> 5;

    #pragma unroll
    for (int i = 0; i < 4; i++) {
        const int r = ty + i * 8;
        t[r][tx] = in[(size_t)(r0 + r) * ldi + c0 + tx];
    }
    __syncthreads();
    #pragma unroll
    for (int i = 0; i < 4; i++) {
        const int r = ty + i * 8;
        out[(size_t)(c0 + r) * ldo + r0 + tx] = t[tx][r];
    }
}

// ------------------------------------------------------------------
// Row stats: one warp per row. m = rowmax, i = 1/sum(exp(x - m)).
// Read-only over scores; writes 2 floats per row.
// ------------------------------------------------------------------
__global__ void __launch_bounds__(256) row_stats(
    const float* __restrict__ S, float* __restrict__ statm,
    float* __restrict__ stati)
{
    const int warp = threadIdx.x >> 5;
    const int lane = threadIdx.x & 31;
    const long long row = (long long)blockIdx.x * 8 + warp;
    const float4* p = (const float4*)(S + row * (long long)SEQ);

    float4 v[8];
    #pragma unroll
    for (int j = 0; j < 8; j++) v[j] = p[lane + j * 32];

    float m = -INFINITY;
    #pragma unroll
    for (int j = 0; j < 8; j++)
        m = fmaxf(m, fmaxf(fmaxf(v[j].x, v[j].y), fmaxf(v[j].z, v[j].w)));
    #pragma unroll
    for (int s = 16; s > 0; s >>= 1)
        m = fmaxf(m, __shfl_xor_sync(0xffffffffu, m, s));

    float sum = 0.f;
    #pragma unroll
    for (int j = 0; j < 8; j++) {
        sum += __expf(v[j].x - m) + __expf(v[j].y - m)
             + __expf(v[j].z - m) + __expf(v[j].w - m);
    }
    #pragma unroll
    for (int s = 16; s > 0; s >>= 1)
        sum += __shfl_xor_sync(0xffffffffu, sum, s);

    if (lane == 0) {
        statm[row] = m;
        stati[row] = 1.0f / sum;
    }
}

// ------------------------------------------------------------------
// Launch
// ------------------------------------------------------------------
extern "C" void kernel_launch(void* const* d_in, const int* in_sizes, int n_in,
                              void* d_out, int out_size)
{
    (void)in_sizes; (void)n_in; (void)out_size;

    const float* layout_x = (const float*)d_in[0];
    const float* text_x   = (const float*)d_in[1];
    const float* mask     = (const float*)d_in[2];
    const float* Wqkv     = (const float*)d_in[3];
    const float* bqkv     = (const float*)d_in[4];
    const float* Wq       = (const float*)d_in[5];
    const float* bq       = (const float*)d_in[6];
    const float* Wkv      = (const float*)d_in[7];
    const float* bkv      = (const float*)d_in[8];
    const float* Wffn     = (const float*)d_in[9];
    const float* bffn     = (const float*)d_in[10];
    float* out = (float*)d_out;

    float *qkv, *scores, *lo, *cq, *kv, *merge;
    float *wqkvT, *wqT, *wkvT, *wffnT, *vT, *cvT, *statm, *stati;
    cudaGetSymbolAddress((void**)&qkv,    g_qkv);
    cudaGetSymbolAddress((void**)&scores, g_scores);
    cudaGetSymbolAddress((void**)&lo,     g_lo);
    cudaGetSymbolAddress((void**)&cq,     g_cq);
    cudaGetSymbolAddress((void**)&kv,     g_kv);
    cudaGetSymbolAddress((void**)&merge,  g_merge);
    cudaGetSymbolAddress((void**)&wqkvT,  g_wqkvT);
    cudaGetSymbolAddress((void**)&wqT,    g_wqT);
    cudaGetSymbolAddress((void**)&wkvT,   g_wkvT);
    cudaGetSymbolAddress((void**)&wffnT,  g_wffnT);
    cudaGetSymbolAddress((void**)&vT,     g_vT);
    cudaGetSymbolAddress((void**)&cvT,    g_cvT);
    cudaGetSymbolAddress((void**)&statm,  g_statm);
    cudaGetSymbolAddress((void**)&stati,  g_stati);

    const float scale = rsqrtf((float)CH);
    const dim3 blk(256);
    const long long sQKV = (long long)SEQ * 3 * CH;
    const long long sS   = (long long)SEQ * SEQ;
    const long long sC   = (long long)SEQ * CH;
    const long long sKV  = (long long)SEQ * 2 * CH;
    const long long sVT  = (long long)CH * SEQ;

    // 0) Weight transposes (once per launch, ~20us total)
    transpose_k<<<dim3(3 * CH / 32, CH / 32, 1), blk>>>(Wqkv, 3 * CH, 0, wqkvT, CH, 0);
    transpose_k<<<dim3(CH / 32, CH / 32, 1), blk>>>(Wq, CH, 0, wqT, CH, 0);
    transpose_k<<<dim3(2 * CH / 32, CH / 32, 1), blk>>>(Wkv, 2 * CH, 0, wkvT, CH, 0);
    transpose_k<<<dim3(CH / 32, CH / 32, 1), blk>>>(Wffn, CH, 0, wffnT, CH, 0);

    // 1) qkv = layout_x @ Wqkv + bqkv
    gemm_nt<false, false><<<dim3(3 * CH / BN, BATCH * SEQ / BM, 1), blk>>>(
        layout_x, CH, 0, wqkvT, CH, 0, bqkv, nullptr, 0.f, nullptr, nullptr,
        qkv, 3 * CH, 0, CH);

    // 1b) vT[b] = V[b]^T
    transpose_k<<<dim3(CH / 32, SEQ / 32, BATCH), blk>>>(
        qkv + 2 * CH, 3 * CH, sQKV, vT, SEQ, sVT);

    // 2) scores = mask(Q @ K^T * scale)
    gemm_nt<true, false><<<dim3(SEQ / BN, SEQ / BM, BATCH), blk>>>(
        qkv + 0, 3 * CH, sQKV, qkv + CH, 3 * CH, sQKV, nullptr, mask, scale,
        nullptr, nullptr, scores, SEQ, sS, CH);

    // 3) row stats (m, 1/l)
    row_stats<<<BATCH * SEQ / 8, blk>>>(scores, statm, stati);

    // 4) layout_o = softmax(scores) @ V   (exp in staging, 1/l in epilogue)
    gemm_nt<false, true><<<dim3(CH / BN, SEQ / BM, BATCH), blk>>>(
        scores, SEQ, sS, vT, SEQ, sVT, nullptr, nullptr, 0.f, statm, stati,
        lo, CH, sC, SEQ);

    // 5) cq = layout_o @ Wq + bq
    gemm_nt<false, false><<<dim3(CH / BN, BATCH * SEQ / BM, 1), blk>>>(
        lo, CH, 0, wqT, CH, 0, bq, nullptr, 0.f, nullptr, nullptr,
        cq, CH, 0, CH);

    // 6) kv = text_x @ Wkv + bkv
    gemm_nt<false, false><<<dim3(2 * CH / BN, BATCH * SEQ / BM, 1), blk>>>(
        text_x, CH, 0, wkvT, CH, 0, bkv, nullptr, 0.f, nullptr, nullptr,
        kv, 2 * CH, 0, CH);

    // 6b) cvT[b] = CV[b]^T
    transpose_k<<<dim3(CH / 32, SEQ / 32, BATCH), blk>>>(
        kv + CH, 2 * CH, sKV, cvT, SEQ, sVT);

    // 7) scores = mask(CQ @ CK^T * scale)
    gemm_nt<true, false><<<dim3(SEQ / BN, SEQ / BM, BATCH), blk>>>(
        cq, CH, sC, kv + 0, 2 * CH, sKV, nullptr, mask, scale,
        nullptr, nullptr, scores, SEQ, sS, CH);

    // 8) row stats
    row_stats<<<BATCH * SEQ / 8, blk>>>(scores, statm, stati);

    // 9) merge = softmax(scores) @ CV
    gemm_nt<false, true><<<dim3(CH / BN, SEQ / BM, BATCH), blk>>>(
        scores, SEQ, sS, cvT, SEQ, sVT, nullptr, nullptr, 0.f, statm, stati,
        merge, CH, sC, SEQ);

    // 10) out = merge @ Wffn + bffn
    gemm_nt<false, false><<<dim3(CH / BN, BATCH * SEQ / BM, 1), blk>>>(
        merge, CH, 0, wffnT, CH, 0, bffn, nullptr, 0.f, nullptr, nullptr,
        out, CH, 0, CH);
}

// round 6
// speedup vs baseline: 1.3256x; 1.3256x over previous
#include <cuda_runtime.h>
#include <math.h>
#include <stdint.h>

// ------------------------------------------------------------------
// Problem constants: B=8, M=1024, C=768
// ------------------------------------------------------------------
#define BATCH 8
#define SEQ   1024
#define CH    768

// Scratch (device globals; allocation-free per harness rules)
__device__ __align__(16) float g_qkv   [BATCH * SEQ * (3 * CH)];
__device__ __align__(16) float g_scores[BATCH * SEQ * SEQ];
__device__ __align__(16) float g_lo    [BATCH * SEQ * CH];
__device__ __align__(16) float g_cq    [BATCH * SEQ * CH];
__device__ __align__(16) float g_kv    [BATCH * SEQ * (2 * CH)];
__device__ __align__(16) float g_merge [BATCH * SEQ * CH];

#define BM 128
#define BN 128
#define BK 16
#define BNP (BN + 8)   // Bs row stride in words: 8c+g4 -> conflict-free

// ------------------------------------------------------------------
// TF32 helpers
// ------------------------------------------------------------------
__device__ __forceinline__ unsigned f2tf32(float x) {
    unsigned u;
    asm("cvt.rna.tf32.f32 %0, %1;" : "=r"(u) : "f"(x));
    return u;
}

__device__ __forceinline__ void mma_tf32(float* d, const unsigned* a, const unsigned* b) {
    asm volatile(
        "mma.sync.aligned.m16n8k8.row.col.f32.tf32.tf32.f32 "
        "{%0,%1,%2,%3}, {%4,%5,%6,%7}, {%8,%9}, {%0,%1,%2,%3};\n"
        : "+f"(d[0]), "+f"(d[1]), "+f"(d[2]), "+f"(d[3])
        : "r"(a[0]), "r"(a[1]), "r"(a[2]), "r"(a[3]),
          "r"(b[0]), "r"(b[1]));
}

// Swizzled k-major tile storage: flat [row*16 + pos],
// pos(k,row) = (((k&3) + (row>>1)) & 3)*4 + (k>>2)
// Conflict-free scalar STS; frag load = one conflict-free LDS.128.
__device__ __forceinline__ void store_tile_swz(unsigned* S, int row, int q, float4 v) {
    const int h = (row >> 1) & 3;
    unsigned* base = S + row * 16 + q;
    base[(((0 + h) & 3) << 2)] = f2tf32(v.x);
    base[(((1 + h) & 3) << 2)] = f2tf32(v.y);
    base[(((2 + h) & 3) << 2)] = f2tf32(v.z);
    base[(((3 + h) & 3) << 2)] = f2tf32(v.w);
}

__device__ __forceinline__ uint4 ld_frag_swz(const unsigned* S, int row, int c) {
    const int g = (c + (row >> 1)) & 3;
    return *(const uint4*)(S + row * 16 + (g << 2));
}

// ------------------------------------------------------------------
// NN: C[m,n] = sum_k A[m,k]*B[k,n] (+ bias[n]); batched via blockIdx.z
// Double-buffered; B staged via STS.128 (conflict-free), Bs padded.
// ------------------------------------------------------------------
__global__ void __launch_bounds__(256, 2) mma_nn(
    const float* __restrict__ A, int lda, long long strideA,
    const float* __restrict__ B, int ldb, long long strideB,
    const float* __restrict__ bias,
    float* __restrict__ C, int ldc, long long strideC,
    int K)
{
    __shared__ unsigned As[2][BM * BK];        // swizzled
    __shared__ unsigned Bs[2][BK][BNP];        // natural [k][n], padded

    const int b = blockIdx.z;
    A += (size_t)b * strideA;
    B += (size_t)b * strideB;
    C += (size_t)b * strideC;

    const int tid  = threadIdx.x;
    const int lane = tid & 31;
    const int wid  = tid >> 5;
    const int wm = wid & 3;
    const int wn = wid >> 2;
    const int m0 = blockIdx.y * BM;
    const int n0 = blockIdx.x * BN;
    const int c  = lane & 3;
    const int g4 = lane >> 2;

    const int ar = tid >> 2, aq = tid & 3;
    const int bk = tid >> 5, bn4 = (tid & 31) << 2;

    const float* Ap = A + (size_t)(m0 + ar) * lda + 4 * aq;
    const float* Bp = B + (size_t)bk * ldb + n0 + bn4;

    float acc[2][8][4];
    #pragma unroll
    for (int i = 0; i < 2; i++)
        #pragma unroll
        for (int j = 0; j < 8; j++)
            #pragma unroll
            for (int q = 0; q < 4; q++) acc[i][j][q] = 0.f;

    // Prologue: stage k-tile 0 into buffer 0
    {
        float4 a0 = *(const float4*)Ap;
        float4 a1 = *(const float4*)(Ap + (size_t)64 * lda);
        float4 b0 = *(const float4*)Bp;
        float4 b1 = *(const float4*)(Bp + (size_t)8 * ldb);
        store_tile_swz(As[0], ar,      aq, a0);
        store_tile_swz(As[0], ar + 64, aq, a1);
        uint4 u0 = make_uint4(f2tf32(b0.x), f2tf32(b0.y), f2tf32(b0.z), f2tf32(b0.w));
        uint4 u1 = make_uint4(f2tf32(b1.x), f2tf32(b1.y), f2tf32(b1.z), f2tf32(b1.w));
        *(uint4*)&Bs[0][bk][bn4]     = u0;
        *(uint4*)&Bs[0][bk + 8][bn4] = u1;
    }
    __syncthreads();

    const int niter = K / BK;
    int buf = 0;
    float4 pa0, pa1, pb0, pb1;

    for (int kt = 0; kt < niter; kt++) {
        const bool has_next = (kt + 1 < niter);
        if (has_next) {
            const float* An = Ap + (kt + 1) * BK;
            pa0 = *(const float4*)An;
            pa1 = *(const float4*)(An + (size_t)64 * lda);
            const float* Bn = Bp + (size_t)(kt + 1) * BK * ldb;
            pb0 = *(const float4*)Bn;
            pb1 = *(const float4*)(Bn + (size_t)8 * ldb);
        }

        const unsigned* Ab = As[buf];

        unsigned af[2][2][4];
        #pragma unroll
        for (int mt = 0; mt < 2; mt++) {
            const int r = wm * 32 + mt * 16 + g4;
            uint4 lo = ld_frag_swz(Ab, r,     c);
            uint4 hi = ld_frag_swz(Ab, r + 8, c);
            af[mt][0][0] = lo.x; af[mt][0][1] = hi.x;
            af[mt][0][2] = lo.y; af[mt][0][3] = hi.y;
            af[mt][1][0] = lo.z; af[mt][1][1] = hi.z;
            af[mt][1][2] = lo.w; af[mt][1][3] = hi.w;
        }

        #pragma unroll
        for (int nt = 0; nt < 8; nt++) {
            const int col = wn * 64 + nt * 8 + g4;
            unsigned b0[2] = { Bs[buf][c][col],     Bs[buf][c + 4][col]  };
            unsigned b1[2] = { Bs[buf][c + 8][col], Bs[buf][c + 12][col] };
            #pragma unroll
            for (int mt = 0; mt < 2; mt++) {
                mma_tf32(acc[mt][nt], af[mt][0], b0);
                mma_tf32(acc[mt][nt], af[mt][1], b1);
            }
        }

        if (has_next) {
            unsigned* An = As[buf ^ 1];
            store_tile_swz(An, ar,      aq, pa0);
            store_tile_swz(An, ar + 64, aq, pa1);
            uint4 u0 = make_uint4(f2tf32(pb0.x), f2tf32(pb0.y), f2tf32(pb0.z), f2tf32(pb0.w));
            uint4 u1 = make_uint4(f2tf32(pb1.x), f2tf32(pb1.y), f2tf32(pb1.z), f2tf32(pb1.w));
            *(uint4*)&Bs[buf ^ 1][bk][bn4]     = u0;
            *(uint4*)&Bs[buf ^ 1][bk + 8][bn4] = u1;
        }
        __syncthreads();
        buf ^= 1;
    }

    #pragma unroll
    for (int mt = 0; mt < 2; mt++) {
        const int r0 = m0 + wm * 32 + mt * 16 + g4;
        #pragma unroll
        for (int nt = 0; nt < 8; nt++) {
            const int col = n0 + wn * 64 + nt * 8 + 2 * c;
            float bx = 0.f, by = 0.f;
            if (bias) { bx = bias[col]; by = bias[col + 1]; }
            float2 v0 = make_float2(acc[mt][nt][0] + bx, acc[mt][nt][1] + by);
            float2 v1 = make_float2(acc[mt][nt][2] + bx, acc[mt][nt][3] + by);
            *(float2*)(C + (size_t)r0 * ldc + col) = v0;
            *(float2*)(C + (size_t)(r0 + 8) * ldc + col) = v1;
        }
    }
}

// ------------------------------------------------------------------
// NT with masked-score epilogue (double-buffered):
// S[m,n] = valid(m,n) ? scale * sum_d A[m,d]*B[n,d] : -10000
// ------------------------------------------------------------------
__global__ void __launch_bounds__(256, 2) mma_nt_mask(
    const float* __restrict__ A, int lda, long long strideA,
    const float* __restrict__ B, int ldb, long long strideB,
    const float* __restrict__ mask,   // [BATCH, SEQ]
    float scale,
    float* __restrict__ C, int ldc, long long strideC,
    int K)
{
    __shared__ unsigned As[2][BM * BK];    // swizzled
    __shared__ unsigned Bs[2][BN * BK];    // swizzled

    const int b = blockIdx.z;
    A += (size_t)b * strideA;
    B += (size_t)b * strideB;
    C += (size_t)b * strideC;
    const float* mrow = mask + (size_t)b * SEQ;

    const int tid  = threadIdx.x;
    const int lane = tid & 31;
    const int wid  = tid >> 5;
    const int wm = wid & 3;
    const int wn = wid >> 2;
    const int m0 = blockIdx.y * BM;
    const int n0 = blockIdx.x * BN;
    const int c  = lane & 3;
    const int g4 = lane >> 2;

    const int ar = tid >> 2, aq = tid & 3;

    const float* Ap = A + (size_t)(m0 + ar) * lda + 4 * aq;
    const float* Bp = B + (size_t)(n0 + ar) * ldb + 4 * aq;

    float acc[2][8][4];
    #pragma unroll
    for (int i = 0; i < 2; i++)
        #pragma unroll
        for (int j = 0; j < 8; j++)
            #pragma unroll
            for (int q = 0; q < 4; q++) acc[i][j][q] = 0.f;

    // Prologue: stage k-tile 0 into buffer 0
    {
        float4 a0 = *(const float4*)Ap;
        float4 a1 = *(const float4*)(Ap + (size_t)64 * lda);
        float4 b0 = *(const float4*)Bp;
        float4 b1 = *(const float4*)(Bp + (size_t)64 * ldb);
        store_tile_swz(As[0], ar,      aq, a0);
        store_tile_swz(As[0], ar + 64, aq, a1);
        store_tile_swz(Bs[0], ar,      aq, b0);
        store_tile_swz(Bs[0], ar + 64, aq, b1);
    }
    __syncthreads();

    const int niter = K / BK;
    int buf = 0;
    float4 pa0, pa1, pb0, pb1;

    for (int kt = 0; kt < niter; kt++) {
        const bool has_next = (kt + 1 < niter);
        if (has_next) {
            const float* An = Ap + (kt + 1) * BK;
            pa0 = *(const float4*)An;
            pa1 = *(const float4*)(An + (size_t)64 * lda);
            const float* Bn = Bp + (kt + 1) * BK;
            pb0 = *(const float4*)Bn;
            pb1 = *(const float4*)(Bn + (size_t)64 * ldb);
        }

        const unsigned* Ab = As[buf];
        const unsigned* Bb = Bs[buf];

        unsigned af[2][2][4];
        #pragma unroll
        for (int mt = 0; mt < 2; mt++) {
            const int r = wm * 32 + mt * 16 + g4;
            uint4 lo = ld_frag_swz(Ab, r,     c);
            uint4 hi = ld_frag_swz(Ab, r + 8, c);
            af[mt][0][0] = lo.x; af[mt][0][1] = hi.x;
            af[mt][0][2] = lo.y; af[mt][0][3] = hi.y;
            af[mt][1][0] = lo.z; af[mt][1][1] = hi.z;
            af[mt][1][2] = lo.w; af[mt][1][3] = hi.w;
        }

        #pragma unroll
        for (int nt = 0; nt < 8; nt++) {
            uint4 bv = ld_frag_swz(Bb, wn * 64 + nt * 8 + g4, c);
            unsigned b0[2] = { bv.x, bv.y };
            unsigned b1[2] = { bv.z, bv.w };
            #pragma unroll
            for (int mt = 0; mt < 2; mt++) {
                mma_tf32(acc[mt][nt], af[mt][0], b0);
                mma_tf32(acc[mt][nt], af[mt][1], b1);
            }
        }

        if (has_next) {
            unsigned* An = As[buf ^ 1];
            unsigned* Bn = Bs[buf ^ 1];
            store_tile_swz(An, ar,      aq, pa0);
            store_tile_swz(An, ar + 64, aq, pa1);
            store_tile_swz(Bn, ar,      aq, pb0);
            store_tile_swz(Bn, ar + 64, aq, pb1);
        }
        __syncthreads();
        buf ^= 1;
    }

    #pragma unroll
    for (int mt = 0; mt < 2; mt++) {
        const int r0 = m0 + wm * 32 + mt * 16 + g4;
        const float mr0 = mrow[r0];
        const float mr1 = mrow[r0 + 8];
        #pragma unroll
        for (int nt = 0; nt < 8; nt++) {
            const int col = n0 + wn * 64 + nt * 8 + 2 * c;
            const float mn0 = mrow[col];
            const float mn1 = mrow[col + 1];
            float2 v0, v1;
            v0.x = (mr0 != 0.f && mn0 != 0.f) ? acc[mt][nt][0] * scale : -10000.f;
            v0.y = (mr0 != 0.f && mn1 != 0.f) ? acc[mt][nt][1] * scale : -10000.f;
            v1.x = (mr1 != 0.f && mn0 != 0.f) ? acc[mt][nt][2] * scale : -10000.f;
            v1.y = (mr1 != 0.f && mn1 != 0.f) ? acc[mt][nt][3] * scale : -10000.f;
            *(float2*)(C + (size_t)r0 * ldc + col) = v0;
            *(float2*)(C + (size_t)(r0 + 8) * ldc + col) = v1;
        }
    }
}

// ------------------------------------------------------------------
// Fast row softmax: one warp per row, row fully register-resident.
// ------------------------------------------------------------------
__global__ void __launch_bounds__(256) softmax_rows_w(float* __restrict__ S)
{
    const int warp = threadIdx.x >> 5;
    const int lane = threadIdx.x & 31;
    const long long row = (long long)blockIdx.x * 8 + warp;
    float4* p = (float4*)(S + row * (long long)SEQ);

    float4 v[8];
    #pragma unroll
    for (int j = 0; j < 8; j++) v[j] = p[lane + j * 32];

    float m = -INFINITY;
    #pragma unroll
    for (int j = 0; j < 8; j++)
        m = fmaxf(m, fmaxf(fmaxf(v[j].x, v[j].y), fmaxf(v[j].z, v[j].w)));
    #pragma unroll
    for (int s = 16; s > 0; s >>= 1)
        m = fmaxf(m, __shfl_xor_sync(0xffffffffu, m, s));

    float sum = 0.f;
    #pragma unroll
    for (int j = 0; j < 8; j++) {
        v[j].x = __expf(v[j].x - m);
        v[j].y = __expf(v[j].y - m);
        v[j].z = __expf(v[j].z - m);
        v[j].w = __expf(v[j].w - m);
        sum += (v[j].x + v[j].y) + (v[j].z + v[j].w);
    }
    #pragma unroll
    for (int s = 16; s > 0; s >>= 1)
        sum += __shfl_xor_sync(0xffffffffu, sum, s);

    const float inv = 1.0f / sum;
    #pragma unroll
    for (int j = 0; j < 8; j++) {
        v[j].x *= inv; v[j].y *= inv; v[j].z *= inv; v[j].w *= inv;
        p[lane + j * 32] = v[j];
    }
}

// ------------------------------------------------------------------
// Launch (identical flow to R4)
// ------------------------------------------------------------------
extern "C" void kernel_launch(void* const* d_in, const int* in_sizes, int n_in,
                              void* d_out, int out_size)
{
    (void)in_sizes; (void)n_in; (void)out_size;

    const float* layout_x = (const float*)d_in[0];
    const float* text_x   = (const float*)d_in[1];
    const float* mask     = (const float*)d_in[2];
    const float* Wqkv     = (const float*)d_in[3];
    const float* bqkv     = (const float*)d_in[4];
    const float* Wq       = (const float*)d_in[5];
    const float* bq       = (const float*)d_in[6];
    const float* Wkv      = (const float*)d_in[7];
    const float* bkv      = (const float*)d_in[8];
    const float* Wffn     = (const float*)d_in[9];
    const float* bffn     = (const float*)d_in[10];
    float* out = (float*)d_out;

    float *qkv, *scores, *lo, *cq, *kv, *merge;
    cudaGetSymbolAddress((void**)&qkv,    g_qkv);
    cudaGetSymbolAddress((void**)&scores, g_scores);
    cudaGetSymbolAddress((void**)&lo,     g_lo);
    cudaGetSymbolAddress((void**)&cq,     g_cq);
    cudaGetSymbolAddress((void**)&kv,     g_kv);
    cudaGetSymbolAddress((void**)&merge,  g_merge);

    const float scale = rsqrtf((float)CH);
    const dim3 blk(256);
    const long long sQKV = (long long)SEQ * 3 * CH;
    const long long sS   = (long long)SEQ * SEQ;
    const long long sC   = (long long)SEQ * CH;
    const long long sKV  = (long long)SEQ * 2 * CH;

    // 1) qkv = layout_x @ Wqkv + bqkv
    mma_nn<<<dim3(3 * CH / BN, BATCH * SEQ / BM, 1), blk>>>(
        layout_x, CH, 0, Wqkv, 3 * CH, 0, bqkv, qkv, 3 * CH, 0, CH);

    // 2) scores = mask(Q @ K^T * scale)
    mma_nt_mask<<<dim3(SEQ / BN, SEQ / BM, BATCH), blk>>>(
        qkv + 0, 3 * CH, sQKV, qkv + CH, 3 * CH, sQKV, mask, scale,
        scores, SEQ, sS, CH);

    // 3) softmax
    softmax_rows_w<<<BATCH * SEQ / 8, blk>>>(scores);

    // 4) layout_o = P @ V
    mma_nn<<<dim3(CH / BN, SEQ / BM, BATCH), blk>>>(
        scores, SEQ, sS, qkv + 2 * CH, 3 * CH, sQKV, nullptr,
        lo, CH, sC, SEQ);

    // 5) cq = layout_o @ Wq + bq
    mma_nn<<<dim3(CH / BN, BATCH * SEQ / BM, 1), blk>>>(
        lo, CH, 0, Wq, CH, 0, bq, cq, CH, 0, CH);

    // 6) kv = text_x @ Wkv + bkv
    mma_nn<<<dim3(2 * CH / BN, BATCH * SEQ / BM, 1), blk>>>(
        text_x, CH, 0, Wkv, 2 * CH, 0, bkv, kv, 2 * CH, 0, CH);

    // 7) scores = mask(CQ @ CK^T * scale)
    mma_nt_mask<<<dim3(SEQ / BN, SEQ / BM, BATCH), blk>>>(
        cq, CH, sC, kv + 0, 2 * CH, sKV, mask, scale,
        scores, SEQ, sS, CH);

    // 8) softmax
    softmax_rows_w<<<BATCH * SEQ / 8, blk>>>(scores);

    // 9) merge = P @ CV
    mma_nn<<<dim3(CH / BN, SEQ / BM, BATCH), blk>>>(
        scores, SEQ, sS, kv + CH, 2 * CH, sKV, nullptr,
        merge, CH, sC, SEQ);

    // 10) out = merge @ Wffn + bffn
    mma_nn<<<dim3(CH / BN, BATCH * SEQ / BM, 1), blk>>>(
        merge, CH, 0, Wffn, CH, 0, bffn, out, CH, 0, CH);
}